// round 4
// baseline (speedup 1.0000x reference)
#include <cuda_runtime.h>
#include <cuda_fp16.h>
#include <cstdint>

#define TOKENS 8192
#define IN_F   4096
#define OUT_F  4096
#define BM 128
#define BN 128
#define BK 64
#define NK_ITERS (IN_F / BK)    // 64
#define LDSR (BK + 8)           // 72 halves = 144B pitch (conflict-free ldmatrix)
#define STAGES 3
#define A_STAGE_ELEMS (BM * LDSR)
#define B_STAGE_ELEMS (BN * LDSR)
#define SMEM_BYTES (STAGES * (A_STAGE_ELEMS + B_STAGE_ELEMS) * 2)

// ---------------- scratch (device globals: allowed; no allocs) -------------
__device__ __align__(16) __half g_Xh[(size_t)TOKENS * IN_F];   // 64 MB fp16 activations
__device__ __align__(16) __half g_Wh[(size_t)OUT_F * IN_F];    // 32 MB fp16 dequant weights

__device__ __forceinline__ uint32_t smem_u32(const void* p) {
    return (uint32_t)__cvta_generic_to_shared(p);
}

__device__ __forceinline__ void ldm_x4(uint32_t& r0, uint32_t& r1,
                                       uint32_t& r2, uint32_t& r3, uint32_t addr) {
    asm volatile("ldmatrix.sync.aligned.m8n8.x4.shared.b16 {%0,%1,%2,%3}, [%4];"
                 : "=r"(r0), "=r"(r1), "=r"(r2), "=r"(r3) : "r"(addr));
}

__device__ __forceinline__ void mma16816(float* c, const uint32_t* a,
                                         uint32_t b0, uint32_t b1) {
    asm volatile(
        "mma.sync.aligned.m16n8k16.row.col.f32.f16.f16.f32 "
        "{%0,%1,%2,%3}, {%4,%5,%6,%7}, {%8,%9}, {%0,%1,%2,%3};"
        : "+f"(c[0]), "+f"(c[1]), "+f"(c[2]), "+f"(c[3])
        : "r"(a[0]), "r"(a[1]), "r"(a[2]), "r"(a[3]), "r"(b0), "r"(b1));
}

// ---------------- prep kernels ---------------------------------------------
__global__ void convert_x_kernel(const float* __restrict__ x) {
    size_t i = (size_t)blockIdx.x * blockDim.x + threadIdx.x;  // one float4
    if (i >= (size_t)TOKENS * IN_F / 4) return;
    float4 v = reinterpret_cast<const float4*>(x)[i];
    __half2* out = reinterpret_cast<__half2*>(g_Xh);
    out[2 * i]     = __floats2half2_rn(v.x, v.y);
    out[2 * i + 1] = __floats2half2_rn(v.z, v.w);
}

__global__ void dequant_w_kernel(const int* __restrict__ wp,
                                 const float* __restrict__ ws) {
    size_t i = (size_t)blockIdx.x * blockDim.x + threadIdx.x;  // one packed byte
    if (i >= (size_t)OUT_F * (IN_F / 2)) return;
    int n = (int)(i >> 11);          // / 2048
    int j = (int)(i & 2047);
    int p = wp[i];
    float s = ws[n * (IN_F / 128) + (j >> 6)];   // group = (2j)/128 = j/64
    float lo = (float)((p & 15) - 8) * s;        // even column 2j
    float hi = (float)(((p >> 4) & 15) - 8) * s; // odd  column 2j+1
    reinterpret_cast<__half2*>(g_Wh)[i] = __floats2half2_rn(lo, hi);
}

// ---------------- HMMA GEMM -------------------------------------------------
// C[M,N] = Xh[M,K] @ Wh[N,K]^T. CTA tile 128x128, BK=64, 3-stage cp.async.
// Refill issued at top of iteration (right after barrier) so loads overlap
// the full compute window. 1D grid with 8-wide column-band raster swizzle
// for wave-compact L2 reuse.
__global__ void __launch_bounds__(256, 2)
gemm_hmma_kernel(float* __restrict__ C) {
    extern __shared__ __align__(16) __half smem[];
    __half* sA = smem;                                 // STAGES x BM x LDSR
    __half* sB = smem + STAGES * A_STAGE_ELEMS;        // STAGES x BN x LDSR

    const int tid = threadIdx.x;
    const int wid = tid >> 5;
    const int lid = tid & 31;
    const int quad = lid >> 3;
    const int l8 = lid & 7;

    // raster swizzle: bands of 8 column-tiles x 64 row-tiles
    const int lin = blockIdx.x;
    const int band = lin >> 9;          // / (8*64)
    const int within = lin & 511;
    const int bx = band * 8 + (within & 7);   // 0..31  (N tiles)
    const int by = within >> 3;               // 0..63  (M tiles)

    const int m0 = by * BM;
    const int n0 = bx * BN;
    const int m_off = (wid & 3) * 32;
    const int n_off = (wid >> 2) * 64;

    const __half* baseA = g_Xh + (size_t)m0 * IN_F;
    const __half* baseB = g_Wh + (size_t)n0 * IN_F;

    float acc[2][8][4];
#pragma unroll
    for (int mi = 0; mi < 2; mi++)
#pragma unroll
        for (int nf = 0; nf < 8; nf++)
#pragma unroll
            for (int r = 0; r < 4; r++) acc[mi][nf][r] = 0.0f;

    // Stage loader: 128 rows x 8 chunks(16B) for A and B; 256 threads ->
    // 4 chunks each per tile. Lanes 0..7 cover one contiguous 128B row.
    auto load_stage = [&](int st, int kc) {
        const __half* pa = baseA + kc * BK;
        const __half* pb = baseB + kc * BK;
        __half* da = sA + st * A_STAGE_ELEMS;
        __half* db = sB + st * B_STAGE_ELEMS;
#pragma unroll
        for (int i = 0; i < 4; i++) {
            int chunk = tid + 256 * i;
            int row = chunk >> 3, ch = chunk & 7;
            uint32_t dsta = smem_u32(da + row * LDSR + ch * 8);
            uint32_t dstb = smem_u32(db + row * LDSR + ch * 8);
            asm volatile("cp.async.cg.shared.global [%0], [%1], 16;"
                         :: "r"(dsta), "l"((const void*)(pa + (size_t)row * IN_F + ch * 8)));
            asm volatile("cp.async.cg.shared.global [%0], [%1], 16;"
                         :: "r"(dstb), "l"((const void*)(pb + (size_t)row * IN_F + ch * 8)));
        }
    };

    load_stage(0, 0);
    asm volatile("cp.async.commit_group;");
    load_stage(1, 1);
    asm volatile("cp.async.commit_group;");

    int cur = 0;
    for (int kc = 0; kc < NK_ITERS; kc++) {
        asm volatile("cp.async.wait_group 1;");   // stage `cur` complete
        __syncthreads();                          // all warps done with stage (cur+2)%3

        // Refill stage consumed one iteration ago — issue FIRST so the loads
        // overlap this whole iteration's compute.
        if (kc + 2 < NK_ITERS) load_stage((cur + 2) % STAGES, kc + 2);
        asm volatile("cp.async.commit_group;");

        const __half* cA = sA + cur * A_STAGE_ELEMS;
        const __half* cB = sB + cur * B_STAGE_ELEMS;

#pragma unroll
        for (int kk = 0; kk < 4; kk++) {
            const int k0 = kk * 16;
            uint32_t a[2][4];
#pragma unroll
            for (int mi = 0; mi < 2; mi++) {
                uint32_t addr = smem_u32(
                    cA + (m_off + mi * 16 + (quad & 1) * 8 + l8) * LDSR
                       + k0 + (quad >> 1) * 8);
                ldm_x4(a[mi][0], a[mi][1], a[mi][2], a[mi][3], addr);
            }
            uint32_t b[4][4];
#pragma unroll
            for (int nb = 0; nb < 4; nb++) {
                uint32_t addr = smem_u32(
                    cB + (n_off + nb * 16 + (quad >> 1) * 8 + l8) * LDSR
                       + k0 + (quad & 1) * 8);
                ldm_x4(b[nb][0], b[nb][1], b[nb][2], b[nb][3], addr);
            }
#pragma unroll
            for (int mi = 0; mi < 2; mi++)
#pragma unroll
                for (int nf = 0; nf < 8; nf++) {
                    const uint32_t* bf = &b[nf >> 1][(nf & 1) * 2];
                    mma16816(acc[mi][nf], a[mi], bf[0], bf[1]);
                }
        }

        cur = (cur + 1) % STAGES;
    }

    // Epilogue: c0,c1 at (row = t/4, col = 2*(t%4)); c2,c3 at row+8.
    const int er = lid >> 2;
    const int ec = (lid & 3) * 2;
#pragma unroll
    for (int mi = 0; mi < 2; mi++) {
        float* r0 = C + (size_t)(m0 + m_off + mi * 16 + er) * OUT_F + n0 + n_off;
        float* r1 = r0 + (size_t)8 * OUT_F;
#pragma unroll
        for (int nf = 0; nf < 8; nf++) {
            float2 v0 = make_float2(acc[mi][nf][0], acc[mi][nf][1]);
            float2 v1 = make_float2(acc[mi][nf][2], acc[mi][nf][3]);
            *reinterpret_cast<float2*>(r0 + nf * 8 + ec) = v0;
            *reinterpret_cast<float2*>(r1 + nf * 8 + ec) = v1;
        }
    }
}

// ---------------- launch -----------------------------------------------------
extern "C" void kernel_launch(void* const* d_in, const int* in_sizes, int n_in,
                              void* d_out, int out_size) {
    const float* x  = (const float*)d_in[0];
    const int*   wp = (const int*)d_in[1];
    const float* ws = (const float*)d_in[2];
    float* out = (float*)d_out;

    cudaFuncSetAttribute(gemm_hmma_kernel,
                         cudaFuncAttributeMaxDynamicSharedMemorySize, SMEM_BYTES);

    {
        size_t n4 = (size_t)TOKENS * IN_F / 4;
        convert_x_kernel<<<(unsigned)((n4 + 255) / 256), 256>>>(x);
    }
    {
        size_t np = (size_t)OUT_F * (IN_F / 2);
        dequant_w_kernel<<<(unsigned)((np + 255) / 256), 256>>>(wp, ws);
    }
    {
        gemm_hmma_kernel<<<2048, 256, SMEM_BYTES>>>(out);
    }
}

// round 7
// speedup vs baseline: 1.1419x; 1.1419x over previous
#include <cuda_runtime.h>
#include <cuda_fp16.h>
#include <cstdint>

#define TOKENS 8192
#define IN_F   4096
#define OUT_F  4096
#define BM 128
#define BN 128
#define BK 64
#define NK_ITERS (IN_F / BK)    // 64
#define LDSR (BK + 8)           // 72 halves = 144B pitch (conflict-free ldmatrix)
#define STAGES 3
#define A_STAGE_ELEMS (BM * LDSR)
#define B_STAGE_ELEMS (BN * LDSR)
#define SMEM_BYTES (STAGES * (A_STAGE_ELEMS + B_STAGE_ELEMS) * 2)

// ---------------- scratch (device globals: allowed; no allocs) -------------
__device__ __align__(16) __half g_Xh[(size_t)TOKENS * IN_F];   // 64 MB fp16 activations
__device__ __align__(16) __half g_Wh[(size_t)OUT_F * IN_F];    // 32 MB fp16 dequant weights

__device__ __forceinline__ uint32_t smem_u32(const void* p) {
    return (uint32_t)__cvta_generic_to_shared(p);
}

__device__ __forceinline__ void ldm_x4(uint32_t& r0, uint32_t& r1,
                                       uint32_t& r2, uint32_t& r3, uint32_t addr) {
    asm volatile("ldmatrix.sync.aligned.m8n8.x4.shared.b16 {%0,%1,%2,%3}, [%4];"
                 : "=r"(r0), "=r"(r1), "=r"(r2), "=r"(r3) : "r"(addr));
}

__device__ __forceinline__ void mma16816(float* c, const uint32_t* a,
                                         uint32_t b0, uint32_t b1) {
    asm volatile(
        "mma.sync.aligned.m16n8k16.row.col.f32.f16.f16.f32 "
        "{%0,%1,%2,%3}, {%4,%5,%6,%7}, {%8,%9}, {%0,%1,%2,%3};"
        : "+f"(c[0]), "+f"(c[1]), "+f"(c[2]), "+f"(c[3])
        : "r"(a[0]), "r"(a[1]), "r"(a[2]), "r"(a[3]), "r"(b0), "r"(b1));
}

// ---------------- prep kernels ---------------------------------------------
__global__ void convert_x_kernel(const float* __restrict__ x) {
    size_t i = (size_t)blockIdx.x * blockDim.x + threadIdx.x;  // one float4
    if (i >= (size_t)TOKENS * IN_F / 4) return;
    float4 v = reinterpret_cast<const float4*>(x)[i];
    __half2* out = reinterpret_cast<__half2*>(g_Xh);
    out[2 * i]     = __floats2half2_rn(v.x, v.y);
    out[2 * i + 1] = __floats2half2_rn(v.z, v.w);
}

__global__ void dequant_w_kernel(const int* __restrict__ wp,
                                 const float* __restrict__ ws) {
    size_t i = (size_t)blockIdx.x * blockDim.x + threadIdx.x;  // one packed byte
    if (i >= (size_t)OUT_F * (IN_F / 2)) return;
    int n = (int)(i >> 11);          // / 2048
    int j = (int)(i & 2047);
    int p = wp[i];
    float s = ws[n * (IN_F / 128) + (j >> 6)];   // group = (2j)/128 = j/64
    float lo = (float)((p & 15) - 8) * s;        // even column 2j
    float hi = (float)(((p >> 4) & 15) - 8) * s; // odd  column 2j+1
    reinterpret_cast<__half2*>(g_Wh)[i] = __floats2half2_rn(lo, hi);
}

// ---------------- HMMA GEMM -------------------------------------------------
// C[M,N] = Xh[M,K] @ Wh[N,K]^T. CTA tile 128x128, BK=64, 3-stage cp.async,
// one __syncthreads per K-iteration. Refill interleaved into the compute
// loop (half after kk=0, half after kk=1) so it neither collides with the
// post-barrier ldmatrix burst nor waits for all compute to finish.
// 8 warps: warp_m = wid&3 (32 rows), warp_n = wid>>2 (64 cols).
__global__ void __launch_bounds__(256, 2)
gemm_hmma_kernel(float* __restrict__ C) {
    extern __shared__ __align__(16) __half smem[];
    __half* sA = smem;                                 // STAGES x BM x LDSR
    __half* sB = smem + STAGES * A_STAGE_ELEMS;        // STAGES x BN x LDSR

    const int tid = threadIdx.x;
    const int wid = tid >> 5;
    const int lid = tid & 31;
    const int quad = lid >> 3;
    const int l8 = lid & 7;
    const int m0 = blockIdx.y * BM;
    const int n0 = blockIdx.x * BN;
    const int m_off = (wid & 3) * 32;
    const int n_off = (wid >> 2) * 64;

    const __half* baseA = g_Xh + (size_t)m0 * IN_F;
    const __half* baseB = g_Wh + (size_t)n0 * IN_F;

    float acc[2][8][4];
#pragma unroll
    for (int mi = 0; mi < 2; mi++)
#pragma unroll
        for (int nf = 0; nf < 8; nf++)
#pragma unroll
            for (int r = 0; r < 4; r++) acc[mi][nf][r] = 0.0f;

    // Stage loader half: 2 of 4 per-thread 16B chunks for A and B each.
    // Lanes 0..7 cover one contiguous 128B row.
    auto load_half = [&](int st, int kc, int half) {
        const __half* pa = baseA + kc * BK;
        const __half* pb = baseB + kc * BK;
        __half* da = sA + st * A_STAGE_ELEMS;
        __half* db = sB + st * B_STAGE_ELEMS;
#pragma unroll
        for (int i = 0; i < 2; i++) {
            int chunk = tid + 256 * (half * 2 + i);
            int row = chunk >> 3, ch = chunk & 7;
            uint32_t dsta = smem_u32(da + row * LDSR + ch * 8);
            uint32_t dstb = smem_u32(db + row * LDSR + ch * 8);
            asm volatile("cp.async.cg.shared.global [%0], [%1], 16;"
                         :: "r"(dsta), "l"((const void*)(pa + (size_t)row * IN_F + ch * 8)));
            asm volatile("cp.async.cg.shared.global [%0], [%1], 16;"
                         :: "r"(dstb), "l"((const void*)(pb + (size_t)row * IN_F + ch * 8)));
        }
    };

    load_half(0, 0, 0); load_half(0, 0, 1);
    asm volatile("cp.async.commit_group;");
    load_half(1, 1, 0); load_half(1, 1, 1);
    asm volatile("cp.async.commit_group;");

    int cur = 0;
    for (int kc = 0; kc < NK_ITERS; kc++) {
        asm volatile("cp.async.wait_group 1;");   // stage `cur` complete
        __syncthreads();                          // all warps done with stage (cur+2)%3

        const __half* cA = sA + cur * A_STAGE_ELEMS;
        const __half* cB = sB + cur * B_STAGE_ELEMS;
        const bool refill = (kc + 2 < NK_ITERS);
        const int next_st = (cur + 2) % STAGES;

#pragma unroll
        for (int kk = 0; kk < 4; kk++) {
            const int k0 = kk * 16;
            uint32_t a[2][4];
#pragma unroll
            for (int mi = 0; mi < 2; mi++) {
                uint32_t addr = smem_u32(
                    cA + (m_off + mi * 16 + (quad & 1) * 8 + l8) * LDSR
                       + k0 + (quad >> 1) * 8);
                ldm_x4(a[mi][0], a[mi][1], a[mi][2], a[mi][3], addr);
            }
            uint32_t b[4][4];
#pragma unroll
            for (int nb = 0; nb < 4; nb++) {
                uint32_t addr = smem_u32(
                    cB + (n_off + nb * 16 + (quad >> 1) * 8 + l8) * LDSR
                       + k0 + (quad & 1) * 8);
                ldm_x4(b[nb][0], b[nb][1], b[nb][2], b[nb][3], addr);
            }
#pragma unroll
            for (int mi = 0; mi < 2; mi++)
#pragma unroll
                for (int nf = 0; nf < 8; nf++) {
                    const uint32_t* bf = &b[nf >> 1][(nf & 1) * 2];
                    mma16816(acc[mi][nf], a[mi], bf[0], bf[1]);
                }

            // Interleaved refill: half after kk=0, half (+commit) after kk=1.
            if (kk == 0 && refill) load_half(next_st, kc + 2, 0);
            if (kk == 1) {
                if (refill) load_half(next_st, kc + 2, 1);
                asm volatile("cp.async.commit_group;");
            }
        }

        cur = (cur + 1) % STAGES;
    }

    // Epilogue: c0,c1 at (row = t/4, col = 2*(t%4)); c2,c3 at row+8.
    const int er = lid >> 2;
    const int ec = (lid & 3) * 2;
#pragma unroll
    for (int mi = 0; mi < 2; mi++) {
        float* r0 = C + (size_t)(m0 + m_off + mi * 16 + er) * OUT_F + n0 + n_off;
        float* r1 = r0 + (size_t)8 * OUT_F;
#pragma unroll
        for (int nf = 0; nf < 8; nf++) {
            float2 v0 = make_float2(acc[mi][nf][0], acc[mi][nf][1]);
            float2 v1 = make_float2(acc[mi][nf][2], acc[mi][nf][3]);
            *reinterpret_cast<float2*>(r0 + nf * 8 + ec) = v0;
            *reinterpret_cast<float2*>(r1 + nf * 8 + ec) = v1;
        }
    }
}

// ---------------- launch -----------------------------------------------------
extern "C" void kernel_launch(void* const* d_in, const int* in_sizes, int n_in,
                              void* d_out, int out_size) {
    const float* x  = (const float*)d_in[0];
    const int*   wp = (const int*)d_in[1];
    const float* ws = (const float*)d_in[2];
    float* out = (float*)d_out;

    cudaFuncSetAttribute(gemm_hmma_kernel,
                         cudaFuncAttributeMaxDynamicSharedMemorySize, SMEM_BYTES);

    {
        size_t n4 = (size_t)TOKENS * IN_F / 4;
        convert_x_kernel<<<(unsigned)((n4 + 255) / 256), 256>>>(x);
    }
    {
        size_t np = (size_t)OUT_F * (IN_F / 2);
        dequant_w_kernel<<<(unsigned)((np + 255) / 256), 256>>>(wp, ws);
    }
    {
        dim3 grid(OUT_F / BN, TOKENS / BM);   // 32 x 64 = 2048 CTAs
        gemm_hmma_kernel<<<grid, 256, SMEM_BYTES>>>(out);
    }
}

// round 8
// speedup vs baseline: 1.1996x; 1.0505x over previous
#include <cuda_runtime.h>
#include <cuda_fp16.h>
#include <cstdint>

#define TOKENS 8192
#define IN_F   4096
#define OUT_F  4096
#define BM 128
#define BN 256
#define BK 64
#define NK_ITERS (IN_F / BK)    // 64
#define LDSR (BK + 8)           // 72 halves = 144B pitch (conflict-free ldmatrix)
#define STAGES 3
#define A_STAGE_ELEMS (BM * LDSR)   // 9216
#define B_STAGE_ELEMS (BN * LDSR)   // 18432
#define SMEM_BYTES (STAGES * (A_STAGE_ELEMS + B_STAGE_ELEMS) * 2)   // 165888

// ---------------- scratch (device globals: allowed; no allocs) -------------
__device__ __align__(16) __half g_Xh[(size_t)TOKENS * IN_F];   // 64 MB fp16 activations
__device__ __align__(16) __half g_Wh[(size_t)OUT_F * IN_F];    // 32 MB fp16 dequant weights

__device__ __forceinline__ uint32_t smem_u32(const void* p) {
    return (uint32_t)__cvta_generic_to_shared(p);
}

__device__ __forceinline__ void ldm_x4(uint32_t& r0, uint32_t& r1,
                                       uint32_t& r2, uint32_t& r3, uint32_t addr) {
    asm volatile("ldmatrix.sync.aligned.m8n8.x4.shared.b16 {%0,%1,%2,%3}, [%4];"
                 : "=r"(r0), "=r"(r1), "=r"(r2), "=r"(r3) : "r"(addr));
}

__device__ __forceinline__ void mma16816(float* c, const uint32_t* a,
                                         uint32_t b0, uint32_t b1) {
    asm volatile(
        "mma.sync.aligned.m16n8k16.row.col.f32.f16.f16.f32 "
        "{%0,%1,%2,%3}, {%4,%5,%6,%7}, {%8,%9}, {%0,%1,%2,%3};"
        : "+f"(c[0]), "+f"(c[1]), "+f"(c[2]), "+f"(c[3])
        : "r"(a[0]), "r"(a[1]), "r"(a[2]), "r"(a[3]), "r"(b0), "r"(b1));
}

// ---------------- prep kernels ---------------------------------------------
__global__ void convert_x_kernel(const float* __restrict__ x) {
    size_t i = (size_t)blockIdx.x * blockDim.x + threadIdx.x;  // one float4
    if (i >= (size_t)TOKENS * IN_F / 4) return;
    float4 v = reinterpret_cast<const float4*>(x)[i];
    __half2* out = reinterpret_cast<__half2*>(g_Xh);
    out[2 * i]     = __floats2half2_rn(v.x, v.y);
    out[2 * i + 1] = __floats2half2_rn(v.z, v.w);
}

__global__ void dequant_w_kernel(const int* __restrict__ wp,
                                 const float* __restrict__ ws) {
    size_t i = (size_t)blockIdx.x * blockDim.x + threadIdx.x;  // one packed byte
    if (i >= (size_t)OUT_F * (IN_F / 2)) return;
    int n = (int)(i >> 11);          // / 2048
    int j = (int)(i & 2047);
    int p = wp[i];
    float s = ws[n * (IN_F / 128) + (j >> 6)];   // group = (2j)/128 = j/64
    float lo = (float)((p & 15) - 8) * s;        // even column 2j
    float hi = (float)(((p >> 4) & 15) - 8) * s; // odd  column 2j+1
    reinterpret_cast<__half2*>(g_Wh)[i] = __floats2half2_rn(lo, hi);
}

// ---------------- HMMA GEMM -------------------------------------------------
// C[M,N] = Xh[M,K] @ Wh[N,K]^T. CTA tile 128x256, 8 warps (2x4), warp tile
// 64x64 (acc 128 regs), BK=64, 3-stage cp.async, one __syncthreads per
// K-iter. Refill split into quarters interleaved across the 4 kk-steps.
__global__ void __launch_bounds__(256, 1)
gemm_hmma_kernel(float* __restrict__ C) {
    extern __shared__ __align__(16) __half smem[];
    __half* sA = smem;                                 // STAGES x BM x LDSR
    __half* sB = smem + STAGES * A_STAGE_ELEMS;        // STAGES x BN x LDSR

    const int tid = threadIdx.x;
    const int wid = tid >> 5;
    const int lid = tid & 31;
    const int quad = lid >> 3;
    const int l8 = lid & 7;
    const int m0 = blockIdx.y * BM;
    const int n0 = blockIdx.x * BN;
    const int m_off = (wid & 1) * 64;      // 2 warp rows
    const int n_off = (wid >> 1) * 64;     // 4 warp cols

    const __half* baseA = g_Xh + (size_t)m0 * IN_F;
    const __half* baseB = g_Wh + (size_t)n0 * IN_F;

    float acc[4][8][4];
#pragma unroll
    for (int mi = 0; mi < 4; mi++)
#pragma unroll
        for (int nf = 0; nf < 8; nf++)
#pragma unroll
            for (int r = 0; r < 4; r++) acc[mi][nf][r] = 0.0f;

    // Stage loader quarters. A: 128 rows x 8 chunks(16B) = 1024 chunks (4/thr);
    // B: 256 rows x 8 = 2048 chunks (8/thr). Quarters: 0: A[0..1], 1: A[2..3],
    // 2: B[0..3], 3: B[4..7]. Lanes 0..7 cover one contiguous 128B row.
    auto load_quarter = [&](int st, int kc, int q) {
        if (q < 2) {
            const __half* pa = baseA + kc * BK;
            __half* da = sA + st * A_STAGE_ELEMS;
#pragma unroll
            for (int i = 0; i < 2; i++) {
                int chunk = tid + 256 * (q * 2 + i);
                int row = chunk >> 3, ch = chunk & 7;
                uint32_t dst = smem_u32(da + row * LDSR + ch * 8);
                asm volatile("cp.async.cg.shared.global [%0], [%1], 16;"
                             :: "r"(dst), "l"((const void*)(pa + (size_t)row * IN_F + ch * 8)));
            }
        } else {
            const __half* pb = baseB + kc * BK;
            __half* db = sB + st * B_STAGE_ELEMS;
#pragma unroll
            for (int i = 0; i < 4; i++) {
                int chunk = tid + 256 * ((q - 2) * 4 + i);
                int row = chunk >> 3, ch = chunk & 7;
                uint32_t dst = smem_u32(db + row * LDSR + ch * 8);
                asm volatile("cp.async.cg.shared.global [%0], [%1], 16;"
                             :: "r"(dst), "l"((const void*)(pb + (size_t)row * IN_F + ch * 8)));
            }
        }
    };

#pragma unroll
    for (int q = 0; q < 4; q++) load_quarter(0, 0, q);
    asm volatile("cp.async.commit_group;");
#pragma unroll
    for (int q = 0; q < 4; q++) load_quarter(1, 1, q);
    asm volatile("cp.async.commit_group;");

    int cur = 0;
    for (int kc = 0; kc < NK_ITERS; kc++) {
        asm volatile("cp.async.wait_group 1;");   // stage `cur` complete
        __syncthreads();                          // all warps done with stage (cur+2)%3

        const __half* cA = sA + cur * A_STAGE_ELEMS;
        const __half* cB = sB + cur * B_STAGE_ELEMS;
        const bool refill = (kc + 2 < NK_ITERS);
        const int next_st = (cur + 2) % STAGES;

#pragma unroll
        for (int kk = 0; kk < 4; kk++) {
            const int k0 = kk * 16;
            uint32_t a[4][4];
#pragma unroll
            for (int mi = 0; mi < 4; mi++) {
                uint32_t addr = smem_u32(
                    cA + (m_off + mi * 16 + (quad & 1) * 8 + l8) * LDSR
                       + k0 + (quad >> 1) * 8);
                ldm_x4(a[mi][0], a[mi][1], a[mi][2], a[mi][3], addr);
            }
            uint32_t b[4][4];
#pragma unroll
            for (int nb = 0; nb < 4; nb++) {
                uint32_t addr = smem_u32(
                    cB + (n_off + nb * 16 + (quad >> 1) * 8 + l8) * LDSR
                       + k0 + (quad & 1) * 8);
                ldm_x4(b[nb][0], b[nb][1], b[nb][2], b[nb][3], addr);
            }
#pragma unroll
            for (int mi = 0; mi < 4; mi++)
#pragma unroll
                for (int nf = 0; nf < 8; nf++) {
                    const uint32_t* bf = &b[nf >> 1][(nf & 1) * 2];
                    mma16816(acc[mi][nf], a[mi], bf[0], bf[1]);
                }

            // Interleaved refill: one quarter per kk-step, commit on the last.
            if (refill) load_quarter(next_st, kc + 2, kk);
            if (kk == 3) asm volatile("cp.async.commit_group;");
        }

        cur = (cur + 1) % STAGES;
    }

    // Epilogue: c0,c1 at (row = t/4, col = 2*(t%4)); c2,c3 at row+8.
    const int er = lid >> 2;
    const int ec = (lid & 3) * 2;
#pragma unroll
    for (int mi = 0; mi < 4; mi++) {
        float* r0 = C + (size_t)(m0 + m_off + mi * 16 + er) * OUT_F + n0 + n_off;
        float* r1 = r0 + (size_t)8 * OUT_F;
#pragma unroll
        for (int nf = 0; nf < 8; nf++) {
            float2 v0 = make_float2(acc[mi][nf][0], acc[mi][nf][1]);
            float2 v1 = make_float2(acc[mi][nf][2], acc[mi][nf][3]);
            *reinterpret_cast<float2*>(r0 + nf * 8 + ec) = v0;
            *reinterpret_cast<float2*>(r1 + nf * 8 + ec) = v1;
        }
    }
}

// ---------------- launch -----------------------------------------------------
extern "C" void kernel_launch(void* const* d_in, const int* in_sizes, int n_in,
                              void* d_out, int out_size) {
    const float* x  = (const float*)d_in[0];
    const int*   wp = (const int*)d_in[1];
    const float* ws = (const float*)d_in[2];
    float* out = (float*)d_out;

    cudaFuncSetAttribute(gemm_hmma_kernel,
                         cudaFuncAttributeMaxDynamicSharedMemorySize, SMEM_BYTES);

    {
        size_t n4 = (size_t)TOKENS * IN_F / 4;
        convert_x_kernel<<<(unsigned)((n4 + 255) / 256), 256>>>(x);
    }
    {
        size_t np = (size_t)OUT_F * (IN_F / 2);
        dequant_w_kernel<<<(unsigned)((np + 255) / 256), 256>>>(wp, ws);
    }
    {
        dim3 grid(OUT_F / BN, TOKENS / BM);   // 16 x 64 = 1024 CTAs
        gemm_hmma_kernel<<<grid, 256, SMEM_BYTES>>>(out);
    }
}